// round 1
// baseline (speedup 1.0000x reference)
#include <cuda_runtime.h>
#include <cuda_bf16.h>
#include <cstdint>

#define HEADS 12
#define HEAD_SIZE 64
#define HIDDEN 768
#define NPROJ 1536        // 2 * HEADS * HEAD_SIZE
#define B_ 8
#define N_ 1024
#define M_TOT (B_ * N_)   // 8192
#define NEGC 1000000000000.0f

// ---------------- scratch (device globals; no allocation allowed) ----------
__device__ __nv_bfloat16 g_q[(size_t)M_TOT * HIDDEN];  // [row][h*64 + d], RoPE'd
__device__ __nv_bfloat16 g_k[(size_t)M_TOT * HIDDEN];
__device__ float g_sin[N_ * 32];
__device__ float g_cos[N_ * 32];

// ---------------- sin/cos table ------------------------------------------
__global__ void rope_table_kernel() {
    int idx = blockIdx.x * blockDim.x + threadIdx.x;
    if (idx >= N_ * 32) return;
    int n = idx >> 5, i = idx & 31;
    float inv = powf(10000.0f, -(float)(2 * i) / 64.0f);
    float ang = (float)n * inv;
    float s, c;
    sincosf(ang, &s, &c);
    g_sin[idx] = s;
    g_cos[idx] = c;
}

// ---------------- mma helper ----------------------------------------------
__device__ __forceinline__ void mma16816(float* d, const uint32_t* a,
                                         const uint32_t* b, const float* c) {
    asm volatile(
        "mma.sync.aligned.m16n8k16.row.col.f32.bf16.bf16.f32 "
        "{%0,%1,%2,%3}, {%4,%5,%6,%7}, {%8,%9}, {%10,%11,%12,%13};\n"
        : "=f"(d[0]), "=f"(d[1]), "=f"(d[2]), "=f"(d[3])
        : "r"(a[0]), "r"(a[1]), "r"(a[2]), "r"(a[3]),
          "r"(b[0]), "r"(b[1]),
          "f"(c[0]), "f"(c[1]), "f"(c[2]), "f"(c[3]));
}

// ---------------- GEMM1: proj = x@W + b, fused RoPE, bf16 q/k out ---------
// Block tile 128x128, BK=32, 8 warps (2m x 4n), warp tile 64x32.
__global__ __launch_bounds__(256) void proj_rope_kernel(
    const float* __restrict__ x, const float* __restrict__ W,
    const float* __restrict__ bias) {
    const int BK = 32;
    __shared__ __nv_bfloat16 As[128][BK + 8];  // [m][k], pitch 40 halves
    __shared__ __nv_bfloat16 Bs[128][BK + 8];  // [n][k] (transposed), pitch 40

    int tid = threadIdx.x;
    int wid = tid >> 5, lane = tid & 31;
    int g = lane >> 2, t = lane & 3;
    int m0 = blockIdx.y * 128;
    int n0 = blockIdx.x * 128;
    int warpRow = (wid >> 2) * 64;
    int warpCol = (wid & 3) * 32;

    float acc[4][4][4];
#pragma unroll
    for (int a = 0; a < 4; a++)
#pragma unroll
        for (int b = 0; b < 4; b++)
#pragma unroll
            for (int c = 0; c < 4; c++) acc[a][b][c] = 0.f;

    int lr = tid >> 3;  // 0..31
    int lc = tid & 7;   // float4 column index

    float4 ra[4], rb[4];
    // prefetch k-tile 0
#pragma unroll
    for (int it = 0; it < 4; it++)
        ra[it] = *(const float4*)(x + (size_t)(m0 + lr + it * 32) * HIDDEN + lc * 4);
#pragma unroll
    for (int it = 0; it < 4; it++)
        rb[it] = *(const float4*)(W + (size_t)lr * NPROJ + n0 + (lc + it * 8) * 4);

    for (int kt = 0; kt < HIDDEN / BK; kt++) {
        // regs -> smem (convert to bf16)
#pragma unroll
        for (int it = 0; it < 4; it++) {
            int r = lr + it * 32;
            *(__nv_bfloat162*)&As[r][lc * 4] = __floats2bfloat162_rn(ra[it].x, ra[it].y);
            *(__nv_bfloat162*)&As[r][lc * 4 + 2] = __floats2bfloat162_rn(ra[it].z, ra[it].w);
        }
#pragma unroll
        for (int it = 0; it < 4; it++) {
            int cc = lc + it * 8;
            Bs[cc * 4 + 0][lr] = __float2bfloat16_rn(rb[it].x);
            Bs[cc * 4 + 1][lr] = __float2bfloat16_rn(rb[it].y);
            Bs[cc * 4 + 2][lr] = __float2bfloat16_rn(rb[it].z);
            Bs[cc * 4 + 3][lr] = __float2bfloat16_rn(rb[it].w);
        }
        __syncthreads();

        if (kt + 1 < HIDDEN / BK) {  // prefetch next k-tile
            int k0 = (kt + 1) * BK;
#pragma unroll
            for (int it = 0; it < 4; it++)
                ra[it] = *(const float4*)(x + (size_t)(m0 + lr + it * 32) * HIDDEN + k0 + lc * 4);
#pragma unroll
            for (int it = 0; it < 4; it++)
                rb[it] = *(const float4*)(W + (size_t)(k0 + lr) * NPROJ + n0 + (lc + it * 8) * 4);
        }

#pragma unroll
        for (int s = 0; s < 2; s++) {
            int k16 = s * 16;
            uint32_t afr[4][4], bfr[4][2];
#pragma unroll
            for (int mi = 0; mi < 4; mi++) {
                int r = warpRow + mi * 16 + g;
                afr[mi][0] = *(const uint32_t*)&As[r][k16 + 2 * t];
                afr[mi][1] = *(const uint32_t*)&As[r + 8][k16 + 2 * t];
                afr[mi][2] = *(const uint32_t*)&As[r][k16 + 2 * t + 8];
                afr[mi][3] = *(const uint32_t*)&As[r + 8][k16 + 2 * t + 8];
            }
#pragma unroll
            for (int ni = 0; ni < 4; ni++) {
                int cc = warpCol + ni * 8 + g;
                bfr[ni][0] = *(const uint32_t*)&Bs[cc][k16 + 2 * t];
                bfr[ni][1] = *(const uint32_t*)&Bs[cc][k16 + 2 * t + 8];
            }
#pragma unroll
            for (int mi = 0; mi < 4; mi++)
#pragma unroll
                for (int ni = 0; ni < 4; ni++)
                    mma16816(acc[mi][ni], afr[mi], bfr[ni], acc[mi][ni]);
        }
        __syncthreads();
    }

    // epilogue: bias + RoPE (interleaved) in registers, store bf16 q/k
#pragma unroll
    for (int mi = 0; mi < 4; mi++) {
        int r0 = m0 + warpRow + mi * 16 + g;
        int r1 = r0 + 8;
        int pos0 = r0 & (N_ - 1);
        int pos1 = r1 & (N_ - 1);
#pragma unroll
        for (int ni = 0; ni < 4; ni++) {
            int col = n0 + warpCol + ni * 8 + 2 * t;  // even-aligned pair
            float b0 = bias[col], b1 = bias[col + 1];
            float c0 = acc[mi][ni][0] + b0;
            float c1 = acc[mi][ni][1] + b1;
            float c2 = acc[mi][ni][2] + b0;
            float c3 = acc[mi][ni][3] + b1;
            int h = col >> 7;
            int off = col & 127;               // <64 -> q part, >=64 -> k part
            int i = (col & 63) >> 1;           // RoPE pair index
            float s0 = g_sin[pos0 * 32 + i], cs0 = g_cos[pos0 * 32 + i];
            float s1 = g_sin[pos1 * 32 + i], cs1 = g_cos[pos1 * 32 + i];
            // out[2i] = p[2i]*cos - p[2i+1]*sin ; out[2i+1] = p[2i+1]*cos + p[2i]*sin
            float v0 = c0 * cs0 - c1 * s0;
            float v1 = c1 * cs0 + c0 * s0;
            float v2 = c2 * cs1 - c3 * s1;
            float v3 = c3 * cs1 + c2 * s1;
            int dcol = h * 64 + (col & 63);
            __nv_bfloat16* dst = (off < 64) ? g_q : g_k;
            *(__nv_bfloat162*)&dst[(size_t)r0 * HIDDEN + dcol] = __floats2bfloat162_rn(v0, v1);
            *(__nv_bfloat162*)&dst[(size_t)r1 * HIDDEN + dcol] = __floats2bfloat162_rn(v2, v3);
        }
    }
}

// ---------------- GEMM2: logits = q . k^T per (b,h), mask+causal+scale ----
// Block: 128x128 output tile, 8 warps (4m x 2n), warp tile 32x64, K=64.
__global__ __launch_bounds__(256) void logits_kernel(
    const float* __restrict__ mask, float* __restrict__ out) {
    __shared__ __nv_bfloat16 Qs[128][72];  // pitch 72 halves -> conflict-free frag loads
    __shared__ __nv_bfloat16 Ks[128][72];
    int tid = threadIdx.x;
    int wid = tid >> 5, lane = tid & 31;
    int g = lane >> 2, t = lane & 3;
    int bh = blockIdx.z;
    int b = bh / HEADS, h = bh - b * HEADS;
    int m0 = blockIdx.y * 128;
    int n0 = blockIdx.x * 128;

    {
        const __nv_bfloat16* qsrc = g_q + (size_t)(b * N_ + m0) * HIDDEN + h * HEAD_SIZE;
        const __nv_bfloat16* ksrc = g_k + (size_t)(b * N_ + n0) * HIDDEN + h * HEAD_SIZE;
#pragma unroll
        for (int it = 0; it < 4; it++) {
            int item = tid + it * 256;  // 1024 uint4 per tile
            int r = item >> 3;
            int c = item & 7;
            *(uint4*)&Qs[r][c * 8] = *(const uint4*)(qsrc + (size_t)r * HIDDEN + c * 8);
            *(uint4*)&Ks[r][c * 8] = *(const uint4*)(ksrc + (size_t)r * HIDDEN + c * 8);
        }
    }
    __syncthreads();

    int wm = (wid >> 1) * 32;
    int wn = (wid & 1) * 64;
    float acc[2][8][4];
#pragma unroll
    for (int a = 0; a < 2; a++)
#pragma unroll
        for (int bb = 0; bb < 8; bb++)
#pragma unroll
            for (int c = 0; c < 4; c++) acc[a][bb][c] = 0.f;

#pragma unroll
    for (int ks = 0; ks < 4; ks++) {
        int k16 = ks * 16;
        uint32_t afr[2][4], bfr[8][2];
#pragma unroll
        for (int mi = 0; mi < 2; mi++) {
            int r = wm + mi * 16 + g;
            afr[mi][0] = *(const uint32_t*)&Qs[r][k16 + 2 * t];
            afr[mi][1] = *(const uint32_t*)&Qs[r + 8][k16 + 2 * t];
            afr[mi][2] = *(const uint32_t*)&Qs[r][k16 + 2 * t + 8];
            afr[mi][3] = *(const uint32_t*)&Qs[r + 8][k16 + 2 * t + 8];
        }
#pragma unroll
        for (int ni = 0; ni < 8; ni++) {
            int cc = wn + ni * 8 + g;
            bfr[ni][0] = *(const uint32_t*)&Ks[cc][k16 + 2 * t];
            bfr[ni][1] = *(const uint32_t*)&Ks[cc][k16 + 2 * t + 8];
        }
#pragma unroll
        for (int mi = 0; mi < 2; mi++)
#pragma unroll
            for (int ni = 0; ni < 8; ni++)
                mma16816(acc[mi][ni], afr[mi], bfr[ni], acc[mi][ni]);
    }

    const float* maskb = mask + b * N_;
    size_t obase = (size_t)(b * HEADS + h) << 20;  // * 1024 * 1024
#pragma unroll
    for (int mi = 0; mi < 2; mi++) {
        int mrow0 = m0 + wm + mi * 16 + g;
        int mrow1 = mrow0 + 8;
        float mq0 = maskb[mrow0], mq1 = maskb[mrow1];
#pragma unroll
        for (int ni = 0; ni < 8; ni++) {
            int n = n0 + wn + ni * 8 + 2 * t;
            float mk0 = maskb[n], mk1 = maskb[n + 1];
            float l00 = acc[mi][ni][0], l01 = acc[mi][ni][1];
            float l10 = acc[mi][ni][2], l11 = acc[mi][ni][3];
            // logits*mq + NEG*(mq-1), then *mk + NEG*(mk-1)
            l00 = l00 * mq0 + NEGC * (mq0 - 1.f);
            l01 = l01 * mq0 + NEGC * (mq0 - 1.f);
            l10 = l10 * mq1 + NEGC * (mq1 - 1.f);
            l11 = l11 * mq1 + NEGC * (mq1 - 1.f);
            l00 = l00 * mk0 + NEGC * (mk0 - 1.f);
            l01 = l01 * mk1 + NEGC * (mk1 - 1.f);
            l10 = l10 * mk0 + NEGC * (mk0 - 1.f);
            l11 = l11 * mk1 + NEGC * (mk1 - 1.f);
            // causal: subtract NEG where n < m (tril k=-1)
            if (n < mrow0) l00 -= NEGC;
            if (n + 1 < mrow0) l01 -= NEGC;
            if (n < mrow1) l10 -= NEGC;
            if (n + 1 < mrow1) l11 -= NEGC;
            l00 *= 0.125f; l01 *= 0.125f; l10 *= 0.125f; l11 *= 0.125f;
            *(float2*)&out[obase + ((size_t)mrow0 << 10) + n] = make_float2(l00, l01);
            *(float2*)&out[obase + ((size_t)mrow1 << 10) + n] = make_float2(l10, l11);
        }
    }
}

// ---------------- launch ---------------------------------------------------
extern "C" void kernel_launch(void* const* d_in, const int* in_sizes, int n_in,
                              void* d_out, int out_size) {
    const float* x = (const float*)d_in[0];
    const float* W = (const float*)d_in[1];
    const float* bias = (const float*)d_in[2];
    const float* mask = (const float*)d_in[3];
    float* out = (float*)d_out;

    rope_table_kernel<<<(N_ * 32 + 255) / 256, 256>>>();
    dim3 g1(NPROJ / 128, M_TOT / 128);        // (12, 64)
    proj_rope_kernel<<<g1, 256>>>(x, W, bias);
    dim3 g2(N_ / 128, N_ / 128, B_ * HEADS);  // (8, 8, 96)
    logits_kernel<<<g2, 256>>>(mask, out);
}

// round 2
// speedup vs baseline: 1.3207x; 1.3207x over previous
#include <cuda_runtime.h>
#include <cuda_bf16.h>
#include <cstdint>

#define HEADS 12
#define HEAD_SIZE 64
#define HIDDEN 768
#define NPROJ 1536        // 2 * HEADS * HEAD_SIZE
#define B_ 8
#define N_ 1024
#define M_TOT (B_ * N_)   // 8192
#define NEGC 1000000000000.0f

// ---------------- scratch (device globals; no allocation allowed) ----------
__device__ __nv_bfloat16 g_q[(size_t)M_TOT * HIDDEN];   // [row][h*64+d], RoPE'd
__device__ __nv_bfloat16 g_k[(size_t)M_TOT * HIDDEN];
__device__ __nv_bfloat16 g_xb[(size_t)M_TOT * HIDDEN];  // bf16 copy of x
__device__ __nv_bfloat16 g_wt[(size_t)NPROJ * HIDDEN];  // W^T bf16: [n][k]
__device__ float g_sin[N_ * 32];
__device__ float g_cos[N_ * 32];

// ---------------- helpers --------------------------------------------------
__device__ __forceinline__ uint32_t smem_u32(const void* p) {
    return (uint32_t)__cvta_generic_to_shared(p);
}
__device__ __forceinline__ void ldsm_x4(uint32_t& r0, uint32_t& r1,
                                        uint32_t& r2, uint32_t& r3, uint32_t a) {
    asm volatile("ldmatrix.sync.aligned.m8n8.x4.shared.b16 {%0,%1,%2,%3}, [%4];\n"
                 : "=r"(r0), "=r"(r1), "=r"(r2), "=r"(r3) : "r"(a));
}
__device__ __forceinline__ void cp16(uint32_t dst, const void* src) {
    asm volatile("cp.async.cg.shared.global [%0], [%1], 16;\n" ::"r"(dst), "l"(src));
}
__device__ __forceinline__ void cp_commit() {
    asm volatile("cp.async.commit_group;\n");
}
template <int N>
__device__ __forceinline__ void cp_wait() {
    asm volatile("cp.async.wait_group %0;\n" ::"n"(N));
}
__device__ __forceinline__ void mma16816(float* d, const uint32_t* a,
                                         const uint32_t* b, const float* c) {
    asm volatile(
        "mma.sync.aligned.m16n8k16.row.col.f32.bf16.bf16.f32 "
        "{%0,%1,%2,%3}, {%4,%5,%6,%7}, {%8,%9}, {%10,%11,%12,%13};\n"
        : "=f"(d[0]), "=f"(d[1]), "=f"(d[2]), "=f"(d[3])
        : "r"(a[0]), "r"(a[1]), "r"(a[2]), "r"(a[3]),
          "r"(b[0]), "r"(b[1]),
          "f"(c[0]), "f"(c[1]), "f"(c[2]), "f"(c[3]));
}

// ---------------- sin/cos table -------------------------------------------
__global__ void rope_table_kernel() {
    int idx = blockIdx.x * blockDim.x + threadIdx.x;
    if (idx >= N_ * 32) return;
    int n = idx >> 5, i = idx & 31;
    float inv = powf(10000.0f, -(float)(2 * i) / 64.0f);
    float ang = (float)n * inv;
    float s, c;
    sincosf(ang, &s, &c);
    g_sin[idx] = s;
    g_cos[idx] = c;
}

// ---------------- convert x -> bf16 ---------------------------------------
__global__ __launch_bounds__(256) void conv_x_kernel(const float* __restrict__ x) {
    size_t i = (size_t)blockIdx.x * 256 + threadIdx.x;  // 8 elems per thread
    const float4* src = (const float4*)x;
    float4 a = src[i * 2], b = src[i * 2 + 1];
    __nv_bfloat162 o0 = __floats2bfloat162_rn(a.x, a.y);
    __nv_bfloat162 o1 = __floats2bfloat162_rn(a.z, a.w);
    __nv_bfloat162 o2 = __floats2bfloat162_rn(b.x, b.y);
    __nv_bfloat162 o3 = __floats2bfloat162_rn(b.z, b.w);
    uint4 v;
    v.x = *(uint32_t*)&o0; v.y = *(uint32_t*)&o1;
    v.z = *(uint32_t*)&o2; v.w = *(uint32_t*)&o3;
    *(uint4*)&g_xb[i * 8] = v;
}

// ---------------- transpose W -> bf16 [n][k] -------------------------------
__global__ void conv_wt_kernel(const float* __restrict__ W) {
    __shared__ float tile[32][33];
    int n0 = blockIdx.x * 32, k0 = blockIdx.y * 32;
    int tx = threadIdx.x, ty = threadIdx.y;  // (32, 8)
#pragma unroll
    for (int j = 0; j < 4; j++)
        tile[ty + j * 8][tx] = W[(size_t)(k0 + ty + j * 8) * NPROJ + n0 + tx];
    __syncthreads();
#pragma unroll
    for (int j = 0; j < 4; j++)
        g_wt[(size_t)(n0 + ty + j * 8) * HIDDEN + k0 + tx] =
            __float2bfloat16_rn(tile[tx][ty + j * 8]);
}

// ---------------- GEMM1: proj = x@W + b, fused RoPE ------------------------
// Block 128x128, BK=32, double-buffered cp.async, ldmatrix fragments.
// 8 warps (2m x 4n), warp tile 64x32.
__global__ __launch_bounds__(256) void proj_rope_kernel(const float* __restrict__ bias) {
    const int BK = 32;
    const int PITCH = 40;  // halves; 80B -> conflict-free LDSM rows
    __shared__ __nv_bfloat16 As[2][128][PITCH];
    __shared__ __nv_bfloat16 Bs[2][128][PITCH];

    int tid = threadIdx.x;
    int wid = tid >> 5, lane = tid & 31;
    int g = lane >> 2, t = lane & 3;
    int m0 = blockIdx.y * 128;
    int n0 = blockIdx.x * 128;
    int warpRow = (wid >> 2) * 64;
    int warpCol = (wid & 3) * 32;

    float acc[4][4][4];
#pragma unroll
    for (int a = 0; a < 4; a++)
#pragma unroll
        for (int b = 0; b < 4; b++)
#pragma unroll
            for (int c = 0; c < 4; c++) acc[a][b][c] = 0.f;

    // cp.async mapping: row = tid>>1, half-sel = tid&1 (two 16B chunks = 32B)
    int lr = tid >> 1;
    int hs = tid & 1;
    const __nv_bfloat16* aSrc = g_xb + (size_t)(m0 + lr) * HIDDEN + hs * 16;
    const __nv_bfloat16* bSrc = g_wt + (size_t)(n0 + lr) * HIDDEN + hs * 16;

    auto loadTile = [&](int kt, int buf) {
        const __nv_bfloat16* ap = aSrc + kt * BK;
        const __nv_bfloat16* bp = bSrc + kt * BK;
        uint32_t da = smem_u32(&As[buf][lr][hs * 16]);
        uint32_t db = smem_u32(&Bs[buf][lr][hs * 16]);
        cp16(da, ap);
        cp16(da + 16, ap + 8);
        cp16(db, bp);
        cp16(db + 16, bp + 8);
    };

    const int NT = HIDDEN / BK;  // 24
    loadTile(0, 0);
    cp_commit();

    for (int kt = 0; kt < NT; kt++) {
        int buf = kt & 1;
        if (kt + 1 < NT) {
            loadTile(kt + 1, buf ^ 1);
            cp_commit();
            cp_wait<1>();
        } else {
            cp_wait<0>();
        }
        __syncthreads();

#pragma unroll
        for (int s = 0; s < 2; s++) {
            int k16 = s * 16;
            uint32_t afr[4][4], bfr[4][2];
#pragma unroll
            for (int mi = 0; mi < 4; mi++) {
                int row = warpRow + mi * 16 + (lane & 15);
                int col = k16 + (lane >> 4) * 8;
                ldsm_x4(afr[mi][0], afr[mi][1], afr[mi][2], afr[mi][3],
                        smem_u32(&As[buf][row][col]));
            }
#pragma unroll
            for (int p = 0; p < 2; p++) {
                int tileIdx = lane >> 3;
                int ni = p * 2 + (tileIdx >> 1);
                int row = warpCol + ni * 8 + (lane & 7);
                int col = k16 + (tileIdx & 1) * 8;
                uint32_t r0, r1, r2, r3;
                ldsm_x4(r0, r1, r2, r3, smem_u32(&Bs[buf][row][col]));
                bfr[p * 2][0] = r0; bfr[p * 2][1] = r1;
                bfr[p * 2 + 1][0] = r2; bfr[p * 2 + 1][1] = r3;
            }
#pragma unroll
            for (int mi = 0; mi < 4; mi++)
#pragma unroll
                for (int ni = 0; ni < 4; ni++)
                    mma16816(acc[mi][ni], afr[mi], bfr[ni], acc[mi][ni]);
        }
        __syncthreads();
    }

    // epilogue: bias + interleaved RoPE in registers, store bf16 q/k
#pragma unroll
    for (int mi = 0; mi < 4; mi++) {
        int r0 = m0 + warpRow + mi * 16 + g;
        int r1 = r0 + 8;
        int pos0 = r0 & (N_ - 1);
        int pos1 = r1 & (N_ - 1);
#pragma unroll
        for (int ni = 0; ni < 4; ni++) {
            int col = n0 + warpCol + ni * 8 + 2 * t;  // even-aligned pair
            float b0 = bias[col], b1 = bias[col + 1];
            float c0 = acc[mi][ni][0] + b0;
            float c1 = acc[mi][ni][1] + b1;
            float c2 = acc[mi][ni][2] + b0;
            float c3 = acc[mi][ni][3] + b1;
            int h = col >> 7;
            int off = col & 127;      // <64 -> q, >=64 -> k
            int i = (col & 63) >> 1;  // RoPE pair index
            float s0 = g_sin[pos0 * 32 + i], cs0 = g_cos[pos0 * 32 + i];
            float s1 = g_sin[pos1 * 32 + i], cs1 = g_cos[pos1 * 32 + i];
            float v0 = c0 * cs0 - c1 * s0;
            float v1 = c1 * cs0 + c0 * s0;
            float v2 = c2 * cs1 - c3 * s1;
            float v3 = c3 * cs1 + c2 * s1;
            int dcol = h * 64 + (col & 63);
            __nv_bfloat16* dst = (off < 64) ? g_q : g_k;
            *(__nv_bfloat162*)&dst[(size_t)r0 * HIDDEN + dcol] = __floats2bfloat162_rn(v0, v1);
            *(__nv_bfloat162*)&dst[(size_t)r1 * HIDDEN + dcol] = __floats2bfloat162_rn(v2, v3);
        }
    }
}

// ---------------- GEMM2: logits = q.k^T, mask+causal+scale -----------------
// Block 128x128, 8 warps (4m x 2n), warp tile 32x64, K=64.
// Blocks strictly below the diagonal skip loads+MMA (|logit| << ulp(1e12)).
__global__ __launch_bounds__(256) void logits_kernel(
    const float* __restrict__ mask, float* __restrict__ out) {
    __shared__ __nv_bfloat16 Qs[128][72];
    __shared__ __nv_bfloat16 Ks[128][72];
    int tid = threadIdx.x;
    int wid = tid >> 5, lane = tid & 31;
    int g = lane >> 2, t = lane & 3;
    int bh = blockIdx.z;
    int b = bh / HEADS, h = bh - b * HEADS;
    int m0 = blockIdx.y * 128;
    int n0 = blockIdx.x * 128;

    int wm = (wid >> 1) * 32;
    int wn = (wid & 1) * 64;
    float acc[2][8][4];
#pragma unroll
    for (int a = 0; a < 2; a++)
#pragma unroll
        for (int bb = 0; bb < 8; bb++)
#pragma unroll
            for (int c = 0; c < 4; c++) acc[a][bb][c] = 0.f;

    bool causal_skip = (blockIdx.x < blockIdx.y);

    if (!causal_skip) {
        const __nv_bfloat16* qsrc = g_q + (size_t)(b * N_ + m0) * HIDDEN + h * HEAD_SIZE;
        const __nv_bfloat16* ksrc = g_k + (size_t)(b * N_ + n0) * HIDDEN + h * HEAD_SIZE;
#pragma unroll
        for (int it = 0; it < 4; it++) {
            int item = tid + it * 256;
            int r = item >> 3;
            int c = item & 7;
            *(uint4*)&Qs[r][c * 8] = *(const uint4*)(qsrc + (size_t)r * HIDDEN + c * 8);
            *(uint4*)&Ks[r][c * 8] = *(const uint4*)(ksrc + (size_t)r * HIDDEN + c * 8);
        }
        __syncthreads();

#pragma unroll
        for (int ks = 0; ks < 4; ks++) {
            int k16 = ks * 16;
            uint32_t afr[2][4], bfr[8][2];
#pragma unroll
            for (int mi = 0; mi < 2; mi++) {
                int row = wm + mi * 16 + (lane & 15);
                int col = k16 + (lane >> 4) * 8;
                ldsm_x4(afr[mi][0], afr[mi][1], afr[mi][2], afr[mi][3],
                        smem_u32(&Qs[row][col]));
            }
#pragma unroll
            for (int p = 0; p < 4; p++) {
                int tileIdx = lane >> 3;
                int ni = p * 2 + (tileIdx >> 1);
                int row = wn + ni * 8 + (lane & 7);
                int col = k16 + (tileIdx & 1) * 8;
                uint32_t r0, r1, r2, r3;
                ldsm_x4(r0, r1, r2, r3, smem_u32(&Ks[row][col]));
                bfr[p * 2][0] = r0; bfr[p * 2][1] = r1;
                bfr[p * 2 + 1][0] = r2; bfr[p * 2 + 1][1] = r3;
            }
#pragma unroll
            for (int mi = 0; mi < 2; mi++)
#pragma unroll
                for (int ni = 0; ni < 8; ni++)
                    mma16816(acc[mi][ni], afr[mi], bfr[ni], acc[mi][ni]);
        }
    }

    const float* maskb = mask + b * N_;
    size_t obase = (size_t)(b * HEADS + h) << 20;
#pragma unroll
    for (int mi = 0; mi < 2; mi++) {
        int mrow0 = m0 + wm + mi * 16 + g;
        int mrow1 = mrow0 + 8;
        float mq0 = maskb[mrow0], mq1 = maskb[mrow1];
#pragma unroll
        for (int ni = 0; ni < 8; ni++) {
            int n = n0 + wn + ni * 8 + 2 * t;
            float mk0 = maskb[n], mk1 = maskb[n + 1];
            float l00 = acc[mi][ni][0], l01 = acc[mi][ni][1];
            float l10 = acc[mi][ni][2], l11 = acc[mi][ni][3];
            l00 = l00 * mq0 + NEGC * (mq0 - 1.f);
            l01 = l01 * mq0 + NEGC * (mq0 - 1.f);
            l10 = l10 * mq1 + NEGC * (mq1 - 1.f);
            l11 = l11 * mq1 + NEGC * (mq1 - 1.f);
            l00 = l00 * mk0 + NEGC * (mk0 - 1.f);
            l01 = l01 * mk1 + NEGC * (mk1 - 1.f);
            l10 = l10 * mk0 + NEGC * (mk0 - 1.f);
            l11 = l11 * mk1 + NEGC * (mk1 - 1.f);
            if (n < mrow0) l00 -= NEGC;
            if (n + 1 < mrow0) l01 -= NEGC;
            if (n < mrow1) l10 -= NEGC;
            if (n + 1 < mrow1) l11 -= NEGC;
            l00 *= 0.125f; l01 *= 0.125f; l10 *= 0.125f; l11 *= 0.125f;
            *(float2*)&out[obase + ((size_t)mrow0 << 10) + n] = make_float2(l00, l01);
            *(float2*)&out[obase + ((size_t)mrow1 << 10) + n] = make_float2(l10, l11);
        }
    }
}

// ---------------- launch ---------------------------------------------------
extern "C" void kernel_launch(void* const* d_in, const int* in_sizes, int n_in,
                              void* d_out, int out_size) {
    const float* x = (const float*)d_in[0];
    const float* W = (const float*)d_in[1];
    const float* bias = (const float*)d_in[2];
    const float* mask = (const float*)d_in[3];
    float* out = (float*)d_out;

    rope_table_kernel<<<(N_ * 32 + 255) / 256, 256>>>();
    conv_x_kernel<<<(int)((size_t)M_TOT * HIDDEN / 8 / 256), 256>>>(x);
    dim3 gt(NPROJ / 32, HIDDEN / 32);
    conv_wt_kernel<<<gt, dim3(32, 8)>>>(W);
    dim3 g1(NPROJ / 128, M_TOT / 128);        // (12, 64)
    proj_rope_kernel<<<g1, 256>>>(bias);
    dim3 g2(N_ / 128, N_ / 128, B_ * HEADS);  // (8, 8, 96)
    logits_kernel<<<g2, 256>>>(mask, out);
}

// round 4
// speedup vs baseline: 1.4236x; 1.0779x over previous
#include <cuda_runtime.h>
#include <cuda_bf16.h>
#include <cstdint>

#define HEADS 12
#define HEAD_SIZE 64
#define HIDDEN 768
#define NPROJ 1536        // 2 * HEADS * HEAD_SIZE
#define B_ 8
#define N_ 1024
#define M_TOT (B_ * N_)   // 8192
#define NEGC 1000000000000.0f
#define NEGS 125000000000.0f   // NEGC / 8

// ---------------- scratch (device globals; no allocation allowed) ----------
__device__ __nv_bfloat16 g_q[(size_t)M_TOT * HIDDEN];   // [row][h*64+d], RoPE'd, pre-scaled by 1/8
__device__ __nv_bfloat16 g_k[(size_t)M_TOT * HIDDEN];
__device__ __nv_bfloat16 g_xb[(size_t)M_TOT * HIDDEN];  // bf16 copy of x
__device__ __nv_bfloat16 g_wt[(size_t)NPROJ * HIDDEN];  // W^T bf16: [n][k]
__device__ float g_sin[N_ * 32];
__device__ float g_cos[N_ * 32];

// ---------------- helpers --------------------------------------------------
__device__ __forceinline__ uint32_t smem_u32(const void* p) {
    return (uint32_t)__cvta_generic_to_shared(p);
}
__device__ __forceinline__ void ldsm_x4(uint32_t& r0, uint32_t& r1,
                                        uint32_t& r2, uint32_t& r3, uint32_t a) {
    asm volatile("ldmatrix.sync.aligned.m8n8.x4.shared.b16 {%0,%1,%2,%3}, [%4];\n"
                 : "=r"(r0), "=r"(r1), "=r"(r2), "=r"(r3) : "r"(a));
}
__device__ __forceinline__ void cp16(uint32_t dst, const void* src) {
    asm volatile("cp.async.cg.shared.global [%0], [%1], 16;\n" ::"r"(dst), "l"(src));
}
__device__ __forceinline__ void cp_commit() {
    asm volatile("cp.async.commit_group;\n");
}
template <int N>
__device__ __forceinline__ void cp_wait() {
    asm volatile("cp.async.wait_group %0;\n" ::"n"(N));
}
__device__ __forceinline__ void mma16816(float* d, const uint32_t* a,
                                         const uint32_t* b, const float* c) {
    asm volatile(
        "mma.sync.aligned.m16n8k16.row.col.f32.bf16.bf16.f32 "
        "{%0,%1,%2,%3}, {%4,%5,%6,%7}, {%8,%9}, {%10,%11,%12,%13};\n"
        : "=f"(d[0]), "=f"(d[1]), "=f"(d[2]), "=f"(d[3])
        : "r"(a[0]), "r"(a[1]), "r"(a[2]), "r"(a[3]),
          "r"(b[0]), "r"(b[1]),
          "f"(c[0]), "f"(c[1]), "f"(c[2]), "f"(c[3]));
}

// ---------------- sin/cos table -------------------------------------------
__global__ void rope_table_kernel() {
    int idx = blockIdx.x * blockDim.x + threadIdx.x;
    if (idx >= N_ * 32) return;
    int n = idx >> 5, i = idx & 31;
    float inv = powf(10000.0f, -(float)(2 * i) / 64.0f);
    float ang = (float)n * inv;
    float s, c;
    sincosf(ang, &s, &c);
    g_sin[idx] = s;
    g_cos[idx] = c;
}

// ---------------- convert x -> bf16 ---------------------------------------
__global__ __launch_bounds__(256) void conv_x_kernel(const float* __restrict__ x) {
    size_t i = (size_t)blockIdx.x * 256 + threadIdx.x;  // 8 elems per thread
    const float4* src = (const float4*)x;
    float4 a = src[i * 2], b = src[i * 2 + 1];
    __nv_bfloat162 o0 = __floats2bfloat162_rn(a.x, a.y);
    __nv_bfloat162 o1 = __floats2bfloat162_rn(a.z, a.w);
    __nv_bfloat162 o2 = __floats2bfloat162_rn(b.x, b.y);
    __nv_bfloat162 o3 = __floats2bfloat162_rn(b.z, b.w);
    uint4 v;
    v.x = *(uint32_t*)&o0; v.y = *(uint32_t*)&o1;
    v.z = *(uint32_t*)&o2; v.w = *(uint32_t*)&o3;
    *(uint4*)&g_xb[i * 8] = v;
}

// ---------------- transpose W -> bf16 [n][k] -------------------------------
__global__ void conv_wt_kernel(const float* __restrict__ W) {
    __shared__ float tile[32][33];
    int n0 = blockIdx.x * 32, k0 = blockIdx.y * 32;
    int tx = threadIdx.x, ty = threadIdx.y;  // (32, 8)
#pragma unroll
    for (int j = 0; j < 4; j++)
        tile[ty + j * 8][tx] = W[(size_t)(k0 + ty + j * 8) * NPROJ + n0 + tx];
    __syncthreads();
#pragma unroll
    for (int j = 0; j < 4; j++)
        g_wt[(size_t)(n0 + ty + j * 8) * HIDDEN + k0 + tx] =
            __float2bfloat16_rn(tile[tx][ty + j * 8]);
}

// ---------------- GEMM1: proj = x@W + b, fused RoPE ------------------------
// Block 128x128, BK=32, 4-stage cp.async, ONE sync per k-iter.
// 8 warps (2m x 4n), warp tile 64x32. q output pre-scaled by 1/8.
#define G1_STAGES 4
#define G1_BK 32
#define G1_NT (HIDDEN / G1_BK)  // 24
#define APITCH 40               // halves; 80B rows, conflict-free LDSM
#define STAGE_BYTES (128 * APITCH * 2)          // 10240 B per matrix-stage
#define G1_OFF_B (G1_STAGES * STAGE_BYTES)      // 40960
#define G1_SMEM (2 * G1_STAGES * STAGE_BYTES)   // 81920

__global__ __launch_bounds__(256, 2) void proj_rope_kernel(const float* __restrict__ bias) {
    extern __shared__ char sm[];
    __nv_bfloat16 (*As)[128][APITCH] =
        reinterpret_cast<__nv_bfloat16(*)[128][APITCH]>(sm);
    __nv_bfloat16 (*Bs)[128][APITCH] =
        reinterpret_cast<__nv_bfloat16(*)[128][APITCH]>(sm + G1_OFF_B);

    int tid = threadIdx.x;
    int wid = tid >> 5, lane = tid & 31;
    int g = lane >> 2, t = lane & 3;
    int m0 = blockIdx.y * 128;
    int n0 = blockIdx.x * 128;
    int warpRow = (wid >> 2) * 64;
    int warpCol = (wid & 3) * 32;

    float acc[4][4][4];
#pragma unroll
    for (int a = 0; a < 4; a++)
#pragma unroll
        for (int b = 0; b < 4; b++)
#pragma unroll
            for (int c = 0; c < 4; c++) acc[a][b][c] = 0.f;

    // loader mapping: row = tid>>1, half-sel = tid&1 (two 16B chunks = 32B row-half)
    int lr = tid >> 1;
    int hs = tid & 1;
    const __nv_bfloat16* aSrc = g_xb + (size_t)(m0 + lr) * HIDDEN + hs * 16;
    const __nv_bfloat16* bSrc = g_wt + (size_t)(n0 + lr) * HIDDEN + hs * 16;

    auto load_stage = [&](int kt, int s) {
        const __nv_bfloat16* ap = aSrc + kt * G1_BK;
        const __nv_bfloat16* bp = bSrc + kt * G1_BK;
        uint32_t da = smem_u32(&As[s][lr][hs * 16]);
        uint32_t db = smem_u32(&Bs[s][lr][hs * 16]);
        cp16(da, ap);
        cp16(da + 16, ap + 8);
        cp16(db, bp);
        cp16(db + 16, bp + 8);
    };

    // prologue: stages 0..2 in flight
    load_stage(0, 0); cp_commit();
    load_stage(1, 1); cp_commit();
    load_stage(2, 2); cp_commit();

    for (int kt = 0; kt < G1_NT; kt++) {
        cp_wait<2>();
        __syncthreads();
        // safe: after the sync every thread finished compute(kt-1), whose
        // buffer == (kt+3)&3. Issue next loads, then compute current stage.
        if (kt + 3 < G1_NT) load_stage(kt + 3, (kt + 3) & 3);
        cp_commit();  // always commit (possibly empty) to keep wait counts valid

        int buf = kt & 3;
#pragma unroll
        for (int s = 0; s < 2; s++) {
            int k16 = s * 16;
            uint32_t afr[4][4], bfr[4][2];
#pragma unroll
            for (int mi = 0; mi < 4; mi++) {
                int row = warpRow + mi * 16 + (lane & 15);
                int col = k16 + (lane >> 4) * 8;
                ldsm_x4(afr[mi][0], afr[mi][1], afr[mi][2], afr[mi][3],
                        smem_u32(&As[buf][row][col]));
            }
#pragma unroll
            for (int p = 0; p < 2; p++) {
                int tileIdx = lane >> 3;
                int ni = p * 2 + (tileIdx >> 1);
                int row = warpCol + ni * 8 + (lane & 7);
                int col = k16 + (tileIdx & 1) * 8;
                uint32_t r0, r1, r2, r3;
                ldsm_x4(r0, r1, r2, r3, smem_u32(&Bs[buf][row][col]));
                bfr[p * 2][0] = r0; bfr[p * 2][1] = r1;
                bfr[p * 2 + 1][0] = r2; bfr[p * 2 + 1][1] = r3;
            }
#pragma unroll
            for (int mi = 0; mi < 4; mi++)
#pragma unroll
                for (int ni = 0; ni < 4; ni++)
                    mma16816(acc[mi][ni], afr[mi], bfr[ni], acc[mi][ni]);
        }
    }

    // epilogue: bias + interleaved RoPE; q gets exact 1/8 pre-scale; bf16 out
#pragma unroll
    for (int mi = 0; mi < 4; mi++) {
        int r0 = m0 + warpRow + mi * 16 + g;
        int r1 = r0 + 8;
        int pos0 = r0 & (N_ - 1);
        int pos1 = r1 & (N_ - 1);
#pragma unroll
        for (int ni = 0; ni < 4; ni++) {
            int col = n0 + warpCol + ni * 8 + 2 * t;  // even-aligned pair
            float b0 = bias[col], b1 = bias[col + 1];
            float c0 = acc[mi][ni][0] + b0;
            float c1 = acc[mi][ni][1] + b1;
            float c2 = acc[mi][ni][2] + b0;
            float c3 = acc[mi][ni][3] + b1;
            int h = col >> 7;
            int off = col & 127;      // <64 -> q, >=64 -> k
            int i = (col & 63) >> 1;  // RoPE pair index
            float s0 = g_sin[pos0 * 32 + i], cs0 = g_cos[pos0 * 32 + i];
            float s1 = g_sin[pos1 * 32 + i], cs1 = g_cos[pos1 * 32 + i];
            float v0 = c0 * cs0 - c1 * s0;
            float v1 = c1 * cs0 + c0 * s0;
            float v2 = c2 * cs1 - c3 * s1;
            float v3 = c3 * cs1 + c2 * s1;
            bool is_q = (off < 64);
            float sc = is_q ? 0.125f : 1.0f;  // exact power-of-2: commutes with bf16 rounding
            v0 *= sc; v1 *= sc; v2 *= sc; v3 *= sc;
            int dcol = h * 64 + (col & 63);
            __nv_bfloat16* dst = is_q ? g_q : g_k;
            *(__nv_bfloat162*)&dst[(size_t)r0 * HIDDEN + dcol] = __floats2bfloat162_rn(v0, v1);
            *(__nv_bfloat162*)&dst[(size_t)r1 * HIDDEN + dcol] = __floats2bfloat162_rn(v2, v3);
        }
    }
}

// ---------------- GEMM2: logits = q.k^T (pre-scaled), mask+causal ----------
// Block 128x128, 8 warps (4m x 2n), warp tile 32x64, K=64.
// Blocks strictly below the diagonal skip loads+MMA (|logit| << ulp(NEGS)).
__global__ __launch_bounds__(256) void logits_kernel(
    const float* __restrict__ mask, float* __restrict__ out) {
    __shared__ __nv_bfloat16 Qs[128][72];
    __shared__ __nv_bfloat16 Ks[128][72];
    int tid = threadIdx.x;
    int wid = tid >> 5, lane = tid & 31;
    int g = lane >> 2, t = lane & 3;
    int bh = blockIdx.z;
    int b = bh / HEADS, h = bh - b * HEADS;
    int m0 = blockIdx.y * 128;
    int n0 = blockIdx.x * 128;

    int wm = (wid >> 1) * 32;
    int wn = (wid & 1) * 64;
    float acc[2][8][4];
#pragma unroll
    for (int a = 0; a < 2; a++)
#pragma unroll
        for (int bb = 0; bb < 8; bb++)
#pragma unroll
            for (int c = 0; c < 4; c++) acc[a][bb][c] = 0.f;

    bool causal_skip = (blockIdx.x < blockIdx.y);

    if (!causal_skip) {
        const __nv_bfloat16* qsrc = g_q + (size_t)(b * N_ + m0) * HIDDEN + h * HEAD_SIZE;
        const __nv_bfloat16* ksrc = g_k + (size_t)(b * N_ + n0) * HIDDEN + h * HEAD_SIZE;
#pragma unroll
        for (int it = 0; it < 4; it++) {
            int item = tid + it * 256;
            int r = item >> 3;
            int c = item & 7;
            *(uint4*)&Qs[r][c * 8] = *(const uint4*)(qsrc + (size_t)r * HIDDEN + c * 8);
            *(uint4*)&Ks[r][c * 8] = *(const uint4*)(ksrc + (size_t)r * HIDDEN + c * 8);
        }
        __syncthreads();

#pragma unroll
        for (int ks = 0; ks < 4; ks++) {
            int k16 = ks * 16;
            uint32_t afr[2][4], bfr[8][2];
#pragma unroll
            for (int mi = 0; mi < 2; mi++) {
                int row = wm + mi * 16 + (lane & 15);
                int col = k16 + (lane >> 4) * 8;
                ldsm_x4(afr[mi][0], afr[mi][1], afr[mi][2], afr[mi][3],
                        smem_u32(&Qs[row][col]));
            }
#pragma unroll
            for (int p = 0; p < 4; p++) {
                int tileIdx = lane >> 3;
                int ni = p * 2 + (tileIdx >> 1);
                int row = wn + ni * 8 + (lane & 7);
                int col = k16 + (tileIdx & 1) * 8;
                uint32_t r0, r1, r2, r3;
                ldsm_x4(r0, r1, r2, r3, smem_u32(&Ks[row][col]));
                bfr[p * 2][0] = r0; bfr[p * 2][1] = r1;
                bfr[p * 2 + 1][0] = r2; bfr[p * 2 + 1][1] = r3;
            }
#pragma unroll
            for (int mi = 0; mi < 2; mi++)
#pragma unroll
                for (int ni = 0; ni < 8; ni++)
                    mma16816(acc[mi][ni], afr[mi], bfr[ni], acc[mi][ni]);
        }
    }

    // out = (l*mq + NEGS*(mq-1))*mk + NEGS*(mk-1) - causal*NEGS
    // (identical to reference expression scaled by 1/8; l is pre-scaled)
    const float* maskb = mask + b * N_;
    size_t obase = (size_t)(b * HEADS + h) << 20;
#pragma unroll
    for (int mi = 0; mi < 2; mi++) {
        int mrow0 = m0 + wm + mi * 16 + g;
        int mrow1 = mrow0 + 8;
        float mq0 = maskb[mrow0], mq1 = maskb[mrow1];
        float pm0 = NEGS * (mq0 - 1.f);
        float pm1 = NEGS * (mq1 - 1.f);
#pragma unroll
        for (int ni = 0; ni < 8; ni++) {
            int n = n0 + wn + ni * 8 + 2 * t;
            float mk0 = maskb[n], mk1 = maskb[n + 1];
            float cn0 = NEGS * (mk0 - 1.f);
            float cn1 = NEGS * (mk1 - 1.f);
            float l00 = fmaf(fmaf(acc[mi][ni][0], mq0, pm0), mk0, cn0);
            float l01 = fmaf(fmaf(acc[mi][ni][1], mq0, pm0), mk1, cn1);
            float l10 = fmaf(fmaf(acc[mi][ni][2], mq1, pm1), mk0, cn0);
            float l11 = fmaf(fmaf(acc[mi][ni][3], mq1, pm1), mk1, cn1);
            if (n < mrow0) l00 -= NEGS;
            if (n + 1 < mrow0) l01 -= NEGS;
            if (n < mrow1) l10 -= NEGS;
            if (n + 1 < mrow1) l11 -= NEGS;
            *(float2*)&out[obase + ((size_t)mrow0 << 10) + n] = make_float2(l00, l01);
            *(float2*)&out[obase + ((size_t)mrow1 << 10) + n] = make_float2(l10, l11);
        }
    }
}

// ---------------- launch ---------------------------------------------------
extern "C" void kernel_launch(void* const* d_in, const int* in_sizes, int n_in,
                              void* d_out, int out_size) {
    const float* x = (const float*)d_in[0];
    const float* W = (const float*)d_in[1];
    const float* bias = (const float*)d_in[2];
    const float* mask = (const float*)d_in[3];
    float* out = (float*)d_out;

    cudaFuncSetAttribute(proj_rope_kernel,
                         cudaFuncAttributeMaxDynamicSharedMemorySize, G1_SMEM);

    rope_table_kernel<<<(N_ * 32 + 255) / 256, 256>>>();
    conv_x_kernel<<<(int)((size_t)M_TOT * HIDDEN / 8 / 256), 256>>>(x);
    dim3 gt(NPROJ / 32, HIDDEN / 32);
    conv_wt_kernel<<<gt, dim3(32, 8)>>>(W);
    dim3 g1(NPROJ / 128, M_TOT / 128);        // (12, 64)
    proj_rope_kernel<<<g1, 256, G1_SMEM>>>(bias);
    dim3 g2(N_ / 128, N_ / 128, B_ * HEADS);  // (8, 8, 96)
    logits_kernel<<<g2, 256>>>(mask, out);
}

// round 10
// speedup vs baseline: 1.4698x; 1.0324x over previous
#include <cuda_runtime.h>
#include <cuda_bf16.h>
#include <cstdint>

#define HEADS 12
#define HEAD_SIZE 64
#define HIDDEN 768
#define NPROJ 1536        // 2 * HEADS * HEAD_SIZE
#define B_ 8
#define N_ 1024
#define M_TOT (B_ * N_)   // 8192
#define NEGC 1000000000000.0f
#define NEGS 125000000000.0f   // NEGC / 8

// ---------------- scratch (device globals; no allocation allowed) ----------
__device__ __nv_bfloat16 g_q[(size_t)M_TOT * HIDDEN];   // RoPE'd, pre-scaled 1/8
__device__ __nv_bfloat16 g_k[(size_t)M_TOT * HIDDEN];
__device__ __nv_bfloat16 g_xb[(size_t)M_TOT * HIDDEN];  // bf16 copy of x
__device__ __nv_bfloat16 g_wt[(size_t)NPROJ * HIDDEN];  // W^T bf16: [n][k]
__device__ float g_sin[N_ * 32];
__device__ float g_cos[N_ * 32];

// ---------------- helpers --------------------------------------------------
__device__ __forceinline__ uint32_t smem_u32(const void* p) {
    return (uint32_t)__cvta_generic_to_shared(p);
}
__device__ __forceinline__ void ldsm_x4(uint32_t& r0, uint32_t& r1,
                                        uint32_t& r2, uint32_t& r3, uint32_t a) {
    asm volatile("ldmatrix.sync.aligned.m8n8.x4.shared.b16 {%0,%1,%2,%3}, [%4];\n"
                 : "=r"(r0), "=r"(r1), "=r"(r2), "=r"(r3) : "r"(a));
}
__device__ __forceinline__ void cp16(uint32_t dst, const void* src) {
    asm volatile("cp.async.cg.shared.global [%0], [%1], 16;\n" ::"r"(dst), "l"(src));
}
__device__ __forceinline__ void cp_commit() {
    asm volatile("cp.async.commit_group;\n");
}
template <int N>
__device__ __forceinline__ void cp_wait() {
    asm volatile("cp.async.wait_group %0;\n" ::"n"(N));
}
__device__ __forceinline__ void mma16816(float* d, const uint32_t* a,
                                         const uint32_t* b, const float* c) {
    asm volatile(
        "mma.sync.aligned.m16n8k16.row.col.f32.bf16.bf16.f32 "
        "{%0,%1,%2,%3}, {%4,%5,%6,%7}, {%8,%9}, {%10,%11,%12,%13};\n"
        : "=f"(d[0]), "=f"(d[1]), "=f"(d[2]), "=f"(d[3])
        : "r"(a[0]), "r"(a[1]), "r"(a[2]), "r"(a[3]),
          "r"(b[0]), "r"(b[1]),
          "f"(c[0]), "f"(c[1]), "f"(c[2]), "f"(c[3]));
}

// ---------------- fused prep: conv_x | conv_wt | rope table ----------------
#define PREP_XB (M_TOT * HIDDEN / 8 / 256)          // 3072 blocks
#define PREP_WT ((NPROJ / 32) * (HIDDEN / 32))      // 1152 blocks
#define PREP_RT (N_ * 32 / 256)                     // 128 blocks
__global__ __launch_bounds__(256) void prep_kernel(const float* __restrict__ x,
                                                   const float* __restrict__ W) {
    __shared__ float tile[32][33];
    int blk = blockIdx.x;
    int tid = threadIdx.x;
    if (blk < PREP_XB) {
        size_t i = (size_t)blk * 256 + tid;
        const float4* src = (const float4*)x;
        float4 a = src[i * 2], b = src[i * 2 + 1];
        __nv_bfloat162 o0 = __floats2bfloat162_rn(a.x, a.y);
        __nv_bfloat162 o1 = __floats2bfloat162_rn(a.z, a.w);
        __nv_bfloat162 o2 = __floats2bfloat162_rn(b.x, b.y);
        __nv_bfloat162 o3 = __floats2bfloat162_rn(b.z, b.w);
        uint4 v;
        v.x = *(uint32_t*)&o0; v.y = *(uint32_t*)&o1;
        v.z = *(uint32_t*)&o2; v.w = *(uint32_t*)&o3;
        *(uint4*)&g_xb[i * 8] = v;
    } else if (blk < PREP_XB + PREP_WT) {
        int wb = blk - PREP_XB;
        int n0 = (wb % (NPROJ / 32)) * 32;
        int k0 = (wb / (NPROJ / 32)) * 32;
        int tx = tid & 31, ty = tid >> 5;  // (32, 8)
#pragma unroll
        for (int j = 0; j < 4; j++)
            tile[ty + j * 8][tx] = W[(size_t)(k0 + ty + j * 8) * NPROJ + n0 + tx];
        __syncthreads();
#pragma unroll
        for (int j = 0; j < 4; j++)
            g_wt[(size_t)(n0 + ty + j * 8) * HIDDEN + k0 + tx] =
                __float2bfloat16_rn(tile[tx][ty + j * 8]);
    } else {
        int idx = (blk - PREP_XB - PREP_WT) * 256 + tid;
        int n = idx >> 5, i = idx & 31;
        float inv = powf(10000.0f, -(float)(2 * i) / 64.0f);
        float ang = (float)n * inv;
        float s, c;
        sincosf(ang, &s, &c);
        g_sin[idx] = s;
        g_cos[idx] = c;
    }
}

// ---------------- GEMM1: proj = x@W + b, fused RoPE ------------------------
// Block 128x128, BK=32, 4-stage cp.async, one sync per k-iter, unrolled x4 so
// stage indices/addresses are compile-time immediates.
#define G1_STAGES 4
#define G1_BK 32
#define G1_NT (HIDDEN / G1_BK)  // 24
#define APITCH 40               // halves; 80B rows, conflict-free LDSM
#define STAGE_BYTES (128 * APITCH * 2)          // 10240 B per matrix-stage
#define G1_OFF_B (G1_STAGES * STAGE_BYTES)      // 40960
#define G1_SMEM (2 * G1_STAGES * STAGE_BYTES)   // 81920

__global__ __launch_bounds__(256, 2) void proj_rope_kernel(const float* __restrict__ bias) {
    extern __shared__ char sm[];
    int tid = threadIdx.x;
    int wid = tid >> 5, lane = tid & 31;
    int g = lane >> 2, t = lane & 3;
    int m0 = blockIdx.y * 128;
    int n0 = blockIdx.x * 128;
    int warpRow = (wid >> 2) * 64;
    int warpCol = (wid & 3) * 32;

    float acc[4][4][4];
#pragma unroll
    for (int a = 0; a < 4; a++)
#pragma unroll
        for (int b = 0; b < 4; b++)
#pragma unroll
            for (int c = 0; c < 4; c++) acc[a][b][c] = 0.f;

    // ---- loader setup: row = tid>>1, half = tid&1 (two 16B chunks) ----
    int lr = tid >> 1;
    int hs = tid & 1;
    const __nv_bfloat16* aSrc = g_xb + (size_t)(m0 + lr) * HIDDEN + hs * 16;
    const __nv_bfloat16* bSrc = g_wt + (size_t)(n0 + lr) * HIDDEN + hs * 16;
    uint32_t sbase = smem_u32(sm);
    uint32_t ldA = sbase + lr * (APITCH * 2) + hs * 32;            // As[0][lr][hs*16]
    uint32_t ldB = sbase + G1_OFF_B + lr * (APITCH * 2) + hs * 32;

    // ---- LDSM base addresses (per-warp constants) ----
    // A frag: row = warpRow + mi*16 + (lane&15), col-byte = (lane>>4)*16 (+koff)
    uint32_t aFr = sbase + (warpRow + (lane & 15)) * (APITCH * 2) + (lane >> 4) * 16;
    // B frag p=0: row = warpCol + (lane>>4)*8 + (lane&7), col-byte = ((lane>>3)&1)*16
    // (FIX: (lane>>4)*8, matching R4's ni = p*2 + (lane>>4) per-lane mapping)
    uint32_t bFr0 = sbase + G1_OFF_B +
                    (warpCol + (lane >> 4) * 8 + (lane & 7)) * (APITCH * 2) +
                    ((lane >> 3) & 1) * 16;
    uint32_t bFr1 = bFr0 + 16 * (APITCH * 2);  // p=1 adds 2*8 rows

#define LOAD_STAGE(KT, S)                                              \
    do {                                                               \
        const __nv_bfloat16* ap = aSrc + (KT) * G1_BK;                 \
        const __nv_bfloat16* bp = bSrc + (KT) * G1_BK;                 \
        cp16(ldA + (S) * STAGE_BYTES, ap);                             \
        cp16(ldA + (S) * STAGE_BYTES + 16, ap + 8);                    \
        cp16(ldB + (S) * STAGE_BYTES, bp);                             \
        cp16(ldB + (S) * STAGE_BYTES + 16, bp + 8);                    \
    } while (0)

    LOAD_STAGE(0, 0); cp_commit();
    LOAD_STAGE(1, 1); cp_commit();
    LOAD_STAGE(2, 2); cp_commit();

    for (int kt4 = 0; kt4 < G1_NT; kt4 += 4) {
#pragma unroll
        for (int u = 0; u < 4; u++) {
            int kt = kt4 + u;  // buf == u (kt4 % 4 == 0)
            cp_wait<2>();
            __syncthreads();
            if (kt + 3 < G1_NT) LOAD_STAGE(kt + 3, (u + 3) & 3);
            cp_commit();

#pragma unroll
            for (int s = 0; s < 2; s++) {
                const uint32_t koff = u * STAGE_BYTES + s * 32;  // k16*2 bytes
                uint32_t afr[4][4], bfr[4][2];
#pragma unroll
                for (int mi = 0; mi < 4; mi++)
                    ldsm_x4(afr[mi][0], afr[mi][1], afr[mi][2], afr[mi][3],
                            aFr + koff + mi * (16 * APITCH * 2));
                {
                    uint32_t r0, r1, r2, r3;
                    ldsm_x4(r0, r1, r2, r3, bFr0 + koff);
                    bfr[0][0] = r0; bfr[0][1] = r1;
                    bfr[1][0] = r2; bfr[1][1] = r3;
                    ldsm_x4(r0, r1, r2, r3, bFr1 + koff);
                    bfr[2][0] = r0; bfr[2][1] = r1;
                    bfr[3][0] = r2; bfr[3][1] = r3;
                }
#pragma unroll
                for (int mi = 0; mi < 4; mi++)
#pragma unroll
                    for (int ni = 0; ni < 4; ni++)
                        mma16816(acc[mi][ni], afr[mi], bfr[ni], acc[mi][ni]);
            }
        }
    }
#undef LOAD_STAGE

    // epilogue: bias + interleaved RoPE; q pre-scaled by exact 1/8; bf16 out
#pragma unroll
    for (int mi = 0; mi < 4; mi++) {
        int r0 = m0 + warpRow + mi * 16 + g;
        int r1 = r0 + 8;
        int pos0 = r0 & (N_ - 1);
        int pos1 = r1 & (N_ - 1);
#pragma unroll
        for (int ni = 0; ni < 4; ni++) {
            int col = n0 + warpCol + ni * 8 + 2 * t;  // even-aligned pair
            float b0 = bias[col], b1 = bias[col + 1];
            float c0 = acc[mi][ni][0] + b0;
            float c1 = acc[mi][ni][1] + b1;
            float c2 = acc[mi][ni][2] + b0;
            float c3 = acc[mi][ni][3] + b1;
            int h = col >> 7;
            int off = col & 127;      // <64 -> q, >=64 -> k
            int i = (col & 63) >> 1;  // RoPE pair index
            float s0 = g_sin[pos0 * 32 + i], cs0 = g_cos[pos0 * 32 + i];
            float s1 = g_sin[pos1 * 32 + i], cs1 = g_cos[pos1 * 32 + i];
            float v0 = c0 * cs0 - c1 * s0;
            float v1 = c1 * cs0 + c0 * s0;
            float v2 = c2 * cs1 - c3 * s1;
            float v3 = c3 * cs1 + c2 * s1;
            bool is_q = (off < 64);
            float sc = is_q ? 0.125f : 1.0f;  // exact pow2: commutes with bf16 rounding
            v0 *= sc; v1 *= sc; v2 *= sc; v3 *= sc;
            int dcol = h * 64 + (col & 63);
            __nv_bfloat16* dst = is_q ? g_q : g_k;
            *(__nv_bfloat162*)&dst[(size_t)r0 * HIDDEN + dcol] = __floats2bfloat162_rn(v0, v1);
            *(__nv_bfloat162*)&dst[(size_t)r1 * HIDDEN + dcol] = __floats2bfloat162_rn(v2, v3);
        }
    }
}

// ---------------- GEMM2: logits = q.k^T (pre-scaled), mask+causal ----------
// Block 128x128, 8 warps (4m x 2n), warp tile 32x64, K=64, cp.async loads.
// Blocks strictly below diagonal skip loads+MMA (|logit| << ulp(NEGS)).
__global__ __launch_bounds__(256) void logits_kernel(
    const float* __restrict__ mask, float* __restrict__ out) {
    __shared__ __nv_bfloat16 Qs[128][72];
    __shared__ __nv_bfloat16 Ks[128][72];
    int tid = threadIdx.x;
    int wid = tid >> 5, lane = tid & 31;
    int g = lane >> 2, t = lane & 3;
    int bh = blockIdx.z;
    int b = bh / HEADS, h = bh - b * HEADS;
    int m0 = blockIdx.y * 128;
    int n0 = blockIdx.x * 128;

    int wm = (wid >> 1) * 32;
    int wn = (wid & 1) * 64;
    float acc[2][8][4];
#pragma unroll
    for (int a = 0; a < 2; a++)
#pragma unroll
        for (int bb = 0; bb < 8; bb++)
#pragma unroll
            for (int c = 0; c < 4; c++) acc[a][bb][c] = 0.f;

    bool causal_skip = (blockIdx.x < blockIdx.y);

    if (!causal_skip) {
        const __nv_bfloat16* qsrc = g_q + (size_t)(b * N_ + m0) * HIDDEN + h * HEAD_SIZE;
        const __nv_bfloat16* ksrc = g_k + (size_t)(b * N_ + n0) * HIDDEN + h * HEAD_SIZE;
#pragma unroll
        for (int it = 0; it < 4; it++) {
            int item = tid + it * 256;
            int r = item >> 3;
            int c = item & 7;
            cp16(smem_u32(&Qs[r][c * 8]), qsrc + (size_t)r * HIDDEN + c * 8);
            cp16(smem_u32(&Ks[r][c * 8]), ksrc + (size_t)r * HIDDEN + c * 8);
        }
        cp_commit();
        cp_wait<0>();
        __syncthreads();

#pragma unroll
        for (int ks = 0; ks < 4; ks++) {
            int k16 = ks * 16;
            uint32_t afr[2][4], bfr[8][2];
#pragma unroll
            for (int mi = 0; mi < 2; mi++) {
                int row = wm + mi * 16 + (lane & 15);
                int col = k16 + (lane >> 4) * 8;
                ldsm_x4(afr[mi][0], afr[mi][1], afr[mi][2], afr[mi][3],
                        smem_u32(&Qs[row][col]));
            }
#pragma unroll
            for (int p = 0; p < 4; p++) {
                int tileIdx = lane >> 3;
                int ni = p * 2 + (tileIdx >> 1);
                int row = wn + ni * 8 + (lane & 7);
                int col = k16 + (tileIdx & 1) * 8;
                uint32_t r0, r1, r2, r3;
                ldsm_x4(r0, r1, r2, r3, smem_u32(&Ks[row][col]));
                bfr[p * 2][0] = r0; bfr[p * 2][1] = r1;
                bfr[p * 2 + 1][0] = r2; bfr[p * 2 + 1][1] = r3;
            }
#pragma unroll
            for (int mi = 0; mi < 2; mi++)
#pragma unroll
                for (int ni = 0; ni < 8; ni++)
                    mma16816(acc[mi][ni], afr[mi], bfr[ni], acc[mi][ni]);
        }
    }

    // out = (l*mq + NEGS*(mq-1))*mk + NEGS*(mk-1) - causal*NEGS
    const float* maskb = mask + b * N_;
    size_t obase = (size_t)(b * HEADS + h) << 20;
#pragma unroll
    for (int mi = 0; mi < 2; mi++) {
        int mrow0 = m0 + wm + mi * 16 + g;
        int mrow1 = mrow0 + 8;
        float mq0 = maskb[mrow0], mq1 = maskb[mrow1];
        float pm0 = NEGS * (mq0 - 1.f);
        float pm1 = NEGS * (mq1 - 1.f);
#pragma unroll
        for (int ni = 0; ni < 8; ni++) {
            int n = n0 + wn + ni * 8 + 2 * t;
            float mk0 = maskb[n], mk1 = maskb[n + 1];
            float cn0 = NEGS * (mk0 - 1.f);
            float cn1 = NEGS * (mk1 - 1.f);
            float l00 = fmaf(fmaf(acc[mi][ni][0], mq0, pm0), mk0, cn0);
            float l01 = fmaf(fmaf(acc[mi][ni][1], mq0, pm0), mk1, cn1);
            float l10 = fmaf(fmaf(acc[mi][ni][2], mq1, pm1), mk0, cn0);
            float l11 = fmaf(fmaf(acc[mi][ni][3], mq1, pm1), mk1, cn1);
            if (n < mrow0) l00 -= NEGS;
            if (n + 1 < mrow0) l01 -= NEGS;
            if (n < mrow1) l10 -= NEGS;
            if (n + 1 < mrow1) l11 -= NEGS;
            *(float2*)&out[obase + ((size_t)mrow0 << 10) + n] = make_float2(l00, l01);
            *(float2*)&out[obase + ((size_t)mrow1 << 10) + n] = make_float2(l10, l11);
        }
    }
}

// ---------------- launch ---------------------------------------------------
extern "C" void kernel_launch(void* const* d_in, const int* in_sizes, int n_in,
                              void* d_out, int out_size) {
    const float* x = (const float*)d_in[0];
    const float* W = (const float*)d_in[1];
    const float* bias = (const float*)d_in[2];
    const float* mask = (const float*)d_in[3];
    float* out = (float*)d_out;

    cudaFuncSetAttribute(proj_rope_kernel,
                         cudaFuncAttributeMaxDynamicSharedMemorySize, G1_SMEM);

    prep_kernel<<<PREP_XB + PREP_WT + PREP_RT, 256>>>(x, W);
    dim3 g1(NPROJ / 128, M_TOT / 128);        // (12, 64)
    proj_rope_kernel<<<g1, 256, G1_SMEM>>>(bias);
    dim3 g2(N_ / 128, N_ / 128, B_ * HEADS);  // (8, 8, 96)
    logits_kernel<<<g2, 256>>>(mask, out);
}

// round 12
// speedup vs baseline: 1.5885x; 1.0808x over previous
#include <cuda_runtime.h>
#include <cuda_bf16.h>
#include <cstdint>

#define HEADS 12
#define HEAD_SIZE 64
#define HIDDEN 768
#define NPROJ 1536        // 2 * HEADS * HEAD_SIZE
#define B_ 8
#define N_ 1024
#define M_TOT (B_ * N_)   // 8192
#define NEGC 1000000000000.0f
#define NEGS 125000000000.0f   // NEGC / 8

// ---------------- scratch (device globals; no allocation allowed) ----------
__device__ __nv_bfloat16 g_q[(size_t)M_TOT * HIDDEN];   // RoPE'd, pre-scaled 1/8
__device__ __nv_bfloat16 g_k[(size_t)M_TOT * HIDDEN];
__device__ __nv_bfloat16 g_xb[(size_t)M_TOT * HIDDEN];  // bf16 copy of x
__device__ __nv_bfloat16 g_wt[(size_t)NPROJ * HIDDEN];  // W^T bf16: [n][k]
__device__ float g_sin[N_ * 32];
__device__ float g_cos[N_ * 32];

// ---------------- helpers --------------------------------------------------
__device__ __forceinline__ uint32_t smem_u32(const void* p) {
    return (uint32_t)__cvta_generic_to_shared(p);
}
__device__ __forceinline__ void ldsm_x4(uint32_t& r0, uint32_t& r1,
                                        uint32_t& r2, uint32_t& r3, uint32_t a) {
    asm volatile("ldmatrix.sync.aligned.m8n8.x4.shared.b16 {%0,%1,%2,%3}, [%4];\n"
                 : "=r"(r0), "=r"(r1), "=r"(r2), "=r"(r3) : "r"(a));
}
__device__ __forceinline__ void cp16(uint32_t dst, const void* src) {
    asm volatile("cp.async.cg.shared.global [%0], [%1], 16;\n" ::"r"(dst), "l"(src));
}
__device__ __forceinline__ void cp_commit() {
    asm volatile("cp.async.commit_group;\n");
}
template <int N>
__device__ __forceinline__ void cp_wait() {
    asm volatile("cp.async.wait_group %0;\n" ::"n"(N));
}
__device__ __forceinline__ void mma16816(float* d, const uint32_t* a,
                                         const uint32_t* b, const float* c) {
    asm volatile(
        "mma.sync.aligned.m16n8k16.row.col.f32.bf16.bf16.f32 "
        "{%0,%1,%2,%3}, {%4,%5,%6,%7}, {%8,%9}, {%10,%11,%12,%13};\n"
        : "=f"(d[0]), "=f"(d[1]), "=f"(d[2]), "=f"(d[3])
        : "r"(a[0]), "r"(a[1]), "r"(a[2]), "r"(a[3]),
          "r"(b[0]), "r"(b[1]),
          "f"(c[0]), "f"(c[1]), "f"(c[2]), "f"(c[3]));
}

// ---------------- fused prep: conv_x | conv_wt | rope table ----------------
#define PREP_XB (M_TOT * HIDDEN / 8 / 256)          // 3072 blocks
#define PREP_WT ((NPROJ / 32) * (HIDDEN / 32))      // 1152 blocks
#define PREP_RT (N_ * 32 / 256)                     // 128 blocks
__global__ __launch_bounds__(256) void prep_kernel(const float* __restrict__ x,
                                                   const float* __restrict__ W) {
    __shared__ float tile[32][33];
    int blk = blockIdx.x;
    int tid = threadIdx.x;
    if (blk < PREP_XB) {
        size_t i = (size_t)blk * 256 + tid;
        const float4* src = (const float4*)x;
        float4 a = src[i * 2], b = src[i * 2 + 1];
        __nv_bfloat162 o0 = __floats2bfloat162_rn(a.x, a.y);
        __nv_bfloat162 o1 = __floats2bfloat162_rn(a.z, a.w);
        __nv_bfloat162 o2 = __floats2bfloat162_rn(b.x, b.y);
        __nv_bfloat162 o3 = __floats2bfloat162_rn(b.z, b.w);
        uint4 v;
        v.x = *(uint32_t*)&o0; v.y = *(uint32_t*)&o1;
        v.z = *(uint32_t*)&o2; v.w = *(uint32_t*)&o3;
        *(uint4*)&g_xb[i * 8] = v;
    } else if (blk < PREP_XB + PREP_WT) {
        int wb = blk - PREP_XB;
        int n0 = (wb % (NPROJ / 32)) * 32;
        int k0 = (wb / (NPROJ / 32)) * 32;
        int tx = tid & 31, ty = tid >> 5;  // (32, 8)
#pragma unroll
        for (int j = 0; j < 4; j++)
            tile[ty + j * 8][tx] = W[(size_t)(k0 + ty + j * 8) * NPROJ + n0 + tx];
        __syncthreads();
#pragma unroll
        for (int j = 0; j < 4; j++)
            g_wt[(size_t)(n0 + ty + j * 8) * HIDDEN + k0 + tx] =
                __float2bfloat16_rn(tile[tx][ty + j * 8]);
    } else {
        int idx = (blk - PREP_XB - PREP_WT) * 256 + tid;
        int n = idx >> 5, i = idx & 31;
        float inv = powf(10000.0f, -(float)(2 * i) / 64.0f);
        float ang = (float)n * inv;
        float s, c;
        sincosf(ang, &s, &c);
        g_sin[idx] = s;
        g_cos[idx] = c;
    }
}

// ---------------- GEMM1: proj = x@W + b, fused RoPE ------------------------
// Block 128x128, BK=64, 3-stage cp.async, one sync per k-iter (12 iters).
// 8 warps (2m x 4n), warp tile 64x32. q output pre-scaled by 1/8.
#define G1_BK 64
#define G1_NT (HIDDEN / G1_BK)  // 12
#define APITCH 72               // halves; 144B rows, conflict-free LDSM
#define ROWB (APITCH * 2)       // 144 bytes per row
#define STAGE_BYTES (128 * ROWB)                // 18432 B per matrix-stage
#define G1_OFF_B (3 * STAGE_BYTES)              // 55296
#define G1_SMEM (2 * 3 * STAGE_BYTES)           // 110592

__global__ __launch_bounds__(256, 2) void proj_rope_kernel(const float* __restrict__ bias) {
    extern __shared__ char sm[];
    int tid = threadIdx.x;
    int wid = tid >> 5, lane = tid & 31;
    int g = lane >> 2, t = lane & 3;
    int m0 = blockIdx.y * 128;
    int n0 = blockIdx.x * 128;
    int warpRow = (wid >> 2) * 64;
    int warpCol = (wid & 3) * 32;

    float acc[4][4][4];
#pragma unroll
    for (int a = 0; a < 4; a++)
#pragma unroll
        for (int b = 0; b < 4; b++)
#pragma unroll
            for (int c = 0; c < 4; c++) acc[a][b][c] = 0.f;

    // ---- loader mapping: row = tid>>3 (+32 per it), chunk col = tid&7 ----
    int lrow = tid >> 3;
    int lc = tid & 7;
    const __nv_bfloat16* aSrc = g_xb + (size_t)(m0 + lrow) * HIDDEN + lc * 8;
    const __nv_bfloat16* bSrc = g_wt + (size_t)(n0 + lrow) * HIDDEN + lc * 8;
    uint32_t sbase = smem_u32(sm);
    uint32_t ldA = sbase + lrow * ROWB + lc * 16;
    uint32_t ldB = sbase + G1_OFF_B + lrow * ROWB + lc * 16;

    // ---- LDSM base addresses (per-warp constants) ----
    uint32_t aFr = sbase + (warpRow + (lane & 15)) * ROWB + (lane >> 4) * 16;
    uint32_t bFr0 = sbase + G1_OFF_B +
                    (warpCol + (lane >> 4) * 8 + (lane & 7)) * ROWB +
                    ((lane >> 3) & 1) * 16;
    uint32_t bFr1 = bFr0 + 16 * ROWB;  // +2 n8-tiles

#define LOAD_STAGE(KT, S)                                                     \
    do {                                                                      \
        const __nv_bfloat16* ap = aSrc + (KT) * G1_BK;                        \
        const __nv_bfloat16* bp = bSrc + (KT) * G1_BK;                        \
        uint32_t da = ldA + (S) * STAGE_BYTES;                                \
        uint32_t db = ldB + (S) * STAGE_BYTES;                                \
        cp16(da, ap);                  cp16(da + 32 * ROWB, ap + 32 * HIDDEN);\
        cp16(da + 64 * ROWB, ap + 64 * HIDDEN);                               \
        cp16(da + 96 * ROWB, ap + 96 * HIDDEN);                               \
        cp16(db, bp);                  cp16(db + 32 * ROWB, bp + 32 * HIDDEN);\
        cp16(db + 64 * ROWB, bp + 64 * HIDDEN);                               \
        cp16(db + 96 * ROWB, bp + 96 * HIDDEN);                               \
    } while (0)

    LOAD_STAGE(0, 0); cp_commit();
    LOAD_STAGE(1, 1); cp_commit();

    for (int kt3 = 0; kt3 < G1_NT; kt3 += 3) {
#pragma unroll
        for (int u = 0; u < 3; u++) {
            int kt = kt3 + u;  // buf == u (kt3 % 3 == 0)
            cp_wait<1>();
            __syncthreads();
            if (kt + 2 < G1_NT) LOAD_STAGE(kt + 2, (u + 2) % 3);
            cp_commit();

#pragma unroll
            for (int s = 0; s < 4; s++) {  // 4 x k16 per BK=64 stage
                const uint32_t koff = u * STAGE_BYTES + s * 32;
                uint32_t afr[4][4], bfr[4][2];
#pragma unroll
                for (int mi = 0; mi < 4; mi++)
                    ldsm_x4(afr[mi][0], afr[mi][1], afr[mi][2], afr[mi][3],
                            aFr + koff + mi * (16 * ROWB));
                {
                    uint32_t r0, r1, r2, r3;
                    ldsm_x4(r0, r1, r2, r3, bFr0 + koff);
                    bfr[0][0] = r0; bfr[0][1] = r1;
                    bfr[1][0] = r2; bfr[1][1] = r3;
                    ldsm_x4(r0, r1, r2, r3, bFr1 + koff);
                    bfr[2][0] = r0; bfr[2][1] = r1;
                    bfr[3][0] = r2; bfr[3][1] = r3;
                }
#pragma unroll
                for (int mi = 0; mi < 4; mi++)
#pragma unroll
                    for (int ni = 0; ni < 4; ni++)
                        mma16816(acc[mi][ni], afr[mi], bfr[ni], acc[mi][ni]);
            }
        }
    }
#undef LOAD_STAGE

    // epilogue: bias + interleaved RoPE; q pre-scaled by exact 1/8; bf16 out
#pragma unroll
    for (int mi = 0; mi < 4; mi++) {
        int r0 = m0 + warpRow + mi * 16 + g;
        int r1 = r0 + 8;
        int pos0 = r0 & (N_ - 1);
        int pos1 = r1 & (N_ - 1);
#pragma unroll
        for (int ni = 0; ni < 4; ni++) {
            int col = n0 + warpCol + ni * 8 + 2 * t;  // even-aligned pair
            float b0 = bias[col], b1 = bias[col + 1];
            float c0 = acc[mi][ni][0] + b0;
            float c1 = acc[mi][ni][1] + b1;
            float c2 = acc[mi][ni][2] + b0;
            float c3 = acc[mi][ni][3] + b1;
            int h = col >> 7;
            int off = col & 127;      // <64 -> q, >=64 -> k
            int i = (col & 63) >> 1;  // RoPE pair index
            float s0 = g_sin[pos0 * 32 + i], cs0 = g_cos[pos0 * 32 + i];
            float s1 = g_sin[pos1 * 32 + i], cs1 = g_cos[pos1 * 32 + i];
            float v0 = c0 * cs0 - c1 * s0;
            float v1 = c1 * cs0 + c0 * s0;
            float v2 = c2 * cs1 - c3 * s1;
            float v3 = c3 * cs1 + c2 * s1;
            bool is_q = (off < 64);
            float sc = is_q ? 0.125f : 1.0f;  // exact pow2: commutes with bf16 rounding
            v0 *= sc; v1 *= sc; v2 *= sc; v3 *= sc;
            int dcol = h * 64 + (col & 63);
            __nv_bfloat16* dst = is_q ? g_q : g_k;
            *(__nv_bfloat162*)&dst[(size_t)r0 * HIDDEN + dcol] = __floats2bfloat162_rn(v0, v1);
            *(__nv_bfloat162*)&dst[(size_t)r1 * HIDDEN + dcol] = __floats2bfloat162_rn(v2, v3);
        }
    }
}

// ---------------- GEMM2: logits = q.k^T (pre-scaled), mask+causal ----------
// Block 128x128, 8 warps (4m x 2n), warp tile 32x64, K=64, cp.async loads.
// Blocks strictly below diagonal skip loads+MMA (|logit| << ulp(NEGS)).
__global__ __launch_bounds__(256) void logits_kernel(
    const float* __restrict__ mask, float* __restrict__ out) {
    __shared__ __nv_bfloat16 Qs[128][72];
    __shared__ __nv_bfloat16 Ks[128][72];
    int tid = threadIdx.x;
    int wid = tid >> 5, lane = tid & 31;
    int g = lane >> 2, t = lane & 3;
    int bh = blockIdx.z;
    int b = bh / HEADS, h = bh - b * HEADS;
    int m0 = blockIdx.y * 128;
    int n0 = blockIdx.x * 128;

    int wm = (wid >> 1) * 32;
    int wn = (wid & 1) * 64;
    float acc[2][8][4];
#pragma unroll
    for (int a = 0; a < 2; a++)
#pragma unroll
        for (int bb = 0; bb < 8; bb++)
#pragma unroll
            for (int c = 0; c < 4; c++) acc[a][bb][c] = 0.f;

    bool causal_skip = (blockIdx.x < blockIdx.y);

    if (!causal_skip) {
        const __nv_bfloat16* qsrc = g_q + (size_t)(b * N_ + m0) * HIDDEN + h * HEAD_SIZE;
        const __nv_bfloat16* ksrc = g_k + (size_t)(b * N_ + n0) * HIDDEN + h * HEAD_SIZE;
#pragma unroll
        for (int it = 0; it < 4; it++) {
            int item = tid + it * 256;
            int r = item >> 3;
            int c = item & 7;
            cp16(smem_u32(&Qs[r][c * 8]), qsrc + (size_t)r * HIDDEN + c * 8);
            cp16(smem_u32(&Ks[r][c * 8]), ksrc + (size_t)r * HIDDEN + c * 8);
        }
        cp_commit();
        cp_wait<0>();
        __syncthreads();

#pragma unroll
        for (int ks = 0; ks < 4; ks++) {
            int k16 = ks * 16;
            uint32_t afr[2][4], bfr[8][2];
#pragma unroll
            for (int mi = 0; mi < 2; mi++) {
                int row = wm + mi * 16 + (lane & 15);
                int col = k16 + (lane >> 4) * 8;
                ldsm_x4(afr[mi][0], afr[mi][1], afr[mi][2], afr[mi][3],
                        smem_u32(&Qs[row][col]));
            }
#pragma unroll
            for (int p = 0; p < 4; p++) {
                int tileIdx = lane >> 3;
                int ni = p * 2 + (tileIdx >> 1);
                int row = wn + ni * 8 + (lane & 7);
                int col = k16 + (tileIdx & 1) * 8;
                uint32_t r0, r1, r2, r3;
                ldsm_x4(r0, r1, r2, r3, smem_u32(&Ks[row][col]));
                bfr[p * 2][0] = r0; bfr[p * 2][1] = r1;
                bfr[p * 2 + 1][0] = r2; bfr[p * 2 + 1][1] = r3;
            }
#pragma unroll
            for (int mi = 0; mi < 2; mi++)
#pragma unroll
                for (int ni = 0; ni < 8; ni++)
                    mma16816(acc[mi][ni], afr[mi], bfr[ni], acc[mi][ni]);
        }
    }

    // out = (l*mq + NEGS*(mq-1))*mk + NEGS*(mk-1) - causal*NEGS
    const float* maskb = mask + b * N_;
    size_t obase = (size_t)(b * HEADS + h) << 20;
#pragma unroll
    for (int mi = 0; mi < 2; mi++) {
        int mrow0 = m0 + wm + mi * 16 + g;
        int mrow1 = mrow0 + 8;
        float mq0 = maskb[mrow0], mq1 = maskb[mrow1];
        float pm0 = NEGS * (mq0 - 1.f);
        float pm1 = NEGS * (mq1 - 1.f);
#pragma unroll
        for (int ni = 0; ni < 8; ni++) {
            int n = n0 + wn + ni * 8 + 2 * t;
            float mk0 = maskb[n], mk1 = maskb[n + 1];
            float cn0 = NEGS * (mk0 - 1.f);
            float cn1 = NEGS * (mk1 - 1.f);
            float l00 = fmaf(fmaf(acc[mi][ni][0], mq0, pm0), mk0, cn0);
            float l01 = fmaf(fmaf(acc[mi][ni][1], mq0, pm0), mk1, cn1);
            float l10 = fmaf(fmaf(acc[mi][ni][2], mq1, pm1), mk0, cn0);
            float l11 = fmaf(fmaf(acc[mi][ni][3], mq1, pm1), mk1, cn1);
            if (n < mrow0) l00 -= NEGS;
            if (n + 1 < mrow0) l01 -= NEGS;
            if (n < mrow1) l10 -= NEGS;
            if (n + 1 < mrow1) l11 -= NEGS;
            *(float2*)&out[obase + ((size_t)mrow0 << 10) + n] = make_float2(l00, l01);
            *(float2*)&out[obase + ((size_t)mrow1 << 10) + n] = make_float2(l10, l11);
        }
    }
}

// ---------------- launch ---------------------------------------------------
extern "C" void kernel_launch(void* const* d_in, const int* in_sizes, int n_in,
                              void* d_out, int out_size) {
    const float* x = (const float*)d_in[0];
    const float* W = (const float*)d_in[1];
    const float* bias = (const float*)d_in[2];
    const float* mask = (const float*)d_in[3];
    float* out = (float*)d_out;

    cudaFuncSetAttribute(proj_rope_kernel,
                         cudaFuncAttributeMaxDynamicSharedMemorySize, G1_SMEM);

    prep_kernel<<<PREP_XB + PREP_WT + PREP_RT, 256>>>(x, W);
    dim3 g1(NPROJ / 128, M_TOT / 128);        // (12, 64)
    proj_rope_kernel<<<g1, 256, G1_SMEM>>>(bias);
    dim3 g2(N_ / 128, N_ / 128, B_ * HEADS);  // (8, 8, 96)
    logits_kernel<<<g2, 256>>>(mask, out);
}